// round 2
// baseline (speedup 1.0000x reference)
#include <cuda_runtime.h>
#include <cuda_bf16.h>
#include <cstdint>

#define N_NEW   8192
#define N_EXIST 32768
#define DIM     512
#define EPSV    1e-8f

// ---------------- device scratch (static; no allocation allowed) -------------
__device__ __nv_bfloat16 g_newb[(size_t)N_NEW * DIM];      // 8 MB
__device__ __nv_bfloat16 g_exb[(size_t)N_EXIST * DIM];     // 32 MB
__device__ float g_nnew[N_NEW];
__device__ float g_rnew[N_NEW];
__device__ float g_nex[N_EXIST];
__device__ float g_rex[N_EXIST];
__device__ float g_pval[(size_t)N_NEW * 128];              // 16 partial top-8 sets / row
__device__ int   g_pidx[(size_t)N_NEW * 128];
__device__ float g_agg[(size_t)N_NEW * DIM];               // 16 MB
__device__ float g_hbuf[(size_t)N_NEW * DIM];              // 16 MB

// ---------------- K1: norms + bf16 conversion --------------------------------
__global__ void k_norm_convert(const float* __restrict__ xn,
                               const float* __restrict__ xe) {
    int row = blockIdx.x;             // 0 .. N_NEW+N_EXIST-1
    int t   = threadIdx.x;            // 128 threads
    bool isnew = row < N_NEW;
    int r = isnew ? row : row - N_NEW;
    const float* src = isnew ? xn + (size_t)r * DIM : xe + (size_t)r * DIM;
    __nv_bfloat16* dst = isnew ? g_newb + (size_t)r * DIM : g_exb + (size_t)r * DIM;

    float4 v = reinterpret_cast<const float4*>(src)[t];
    float s = v.x * v.x + v.y * v.y + v.z * v.z + v.w * v.w;

    __nv_bfloat162 p0, p1;
    p0.x = __float2bfloat16(v.x); p0.y = __float2bfloat16(v.y);
    p1.x = __float2bfloat16(v.z); p1.y = __float2bfloat16(v.w);
    reinterpret_cast<__nv_bfloat162*>(dst)[t * 2]     = p0;
    reinterpret_cast<__nv_bfloat162*>(dst)[t * 2 + 1] = p1;

    #pragma unroll
    for (int o = 16; o > 0; o >>= 1) s += __shfl_xor_sync(0xffffffffu, s, o);
    __shared__ float red[4];
    if ((t & 31) == 0) red[t >> 5] = s;
    __syncthreads();
    if (t == 0) {
        float n = sqrtf(red[0] + red[1] + red[2] + red[3]);
        if (isnew) { g_nnew[r] = n; g_rnew[r] = 1.0f / n; }
        else       { g_nex[r]  = n; g_rex[r]  = 1.0f / n; }
    }
}

// ---------------- K2: fused bf16 MMA sim + per-row partial top-8 -------------
#define MT 128      // rows / CTA
#define NT 128      // cols / n-iter
#define NSPLIT 8
#define NITER (N_EXIST / (NSPLIT * NT))   // 32
#define ASTR 520    // bf16 elems (pad: conflict-free frag loads)
#define BSTR 72
#define STSTR 68
#define SMEM_A   (MT * ASTR * 2)                 // 133120
#define SMEM_B1  (NT * BSTR * 2)                 // 18432
#define SMEM_ST  (MT * STSTR * 4)                // 34816
#define SMEM_K2  (SMEM_A + 2 * SMEM_B1 + SMEM_ST + 1024)   // 205824

__device__ __forceinline__ void mma16816(float* c, const uint32_t* a, const uint32_t* b) {
    asm volatile(
        "mma.sync.aligned.m16n8k16.row.col.f32.bf16.bf16.f32 "
        "{%0,%1,%2,%3},{%4,%5,%6,%7},{%8,%9},{%0,%1,%2,%3};"
        : "+f"(c[0]), "+f"(c[1]), "+f"(c[2]), "+f"(c[3])
        : "r"(a[0]), "r"(a[1]), "r"(a[2]), "r"(a[3]), "r"(b[0]), "r"(b[1]));
}
__device__ __forceinline__ void cp16(void* smem, const void* gptr) {
    unsigned s = (unsigned)__cvta_generic_to_shared(smem);
    asm volatile("cp.async.cg.shared.global [%0],[%1],16;\n" :: "r"(s), "l"(gptr));
}

__global__ void __launch_bounds__(256, 1) k_sim_topk() {
    extern __shared__ unsigned char sraw[];
    __nv_bfloat16* As  = (__nv_bfloat16*)sraw;
    __nv_bfloat16* Bs0 = (__nv_bfloat16*)(sraw + SMEM_A);
    __nv_bfloat16* Bs1 = (__nv_bfloat16*)(sraw + SMEM_A + SMEM_B1);
    float* stage = (float*)(sraw + SMEM_A + 2 * SMEM_B1);
    float* rnw   = (float*)(sraw + SMEM_A + 2 * SMEM_B1 + SMEM_ST);
    float* rex   = rnw + 128;

    const int tid  = threadIdx.x;
    const int warp = tid >> 5, lane = tid & 31;
    const int wm = warp & 1, wn = warp >> 1;
    const int g = lane >> 2, tg = lane & 3;
    const int m0 = blockIdx.x * MT;
    const int split = blockIdx.y;
    const int h_own = wn >> 1;

    // resident A tile (128 x 512 bf16, padded stride)
    for (int i = tid; i < MT * 64; i += 256) {
        int r = i >> 6, c = i & 63;
        *(uint4*)(As + r * ASTR + c * 8) =
            *(const uint4*)(g_newb + (size_t)(m0 + r) * DIM + c * 8);
    }
    if (tid < MT) rnw[tid] = g_rnew[m0 + tid];
    __syncthreads();

    const int rloc = tid & 127, par = tid >> 7;
    float tv[8]; int ti[8];
    #pragma unroll
    for (int q = 0; q < 8; q++) { tv[q] = -1e30f; ti[q] = 0; }

    const __nv_bfloat16* Ab = As + (wm * 64 + g) * ASTR + tg * 2;

    #pragma unroll 1
    for (int it = 0; it < NITER; ++it) {
        const int n0 = split * (NT * NITER) + it * NT;
        if (tid < NT) rex[tid] = g_rex[n0 + tid];

        float acc[4][4][4];
        #pragma unroll
        for (int a = 0; a < 4; a++)
            #pragma unroll
            for (int b = 0; b < 4; b++)
                #pragma unroll
                for (int c = 0; c < 4; c++) acc[a][b][c] = 0.f;

        // prefetch k-chunk 0
        for (int i = tid; i < 1024; i += 256) {
            int r = i >> 3, c = i & 7;
            cp16(Bs0 + r * BSTR + c * 8,
                 g_exb + (size_t)(n0 + r) * DIM + c * 8);
        }
        asm volatile("cp.async.commit_group;\n");

        #pragma unroll 1
        for (int kc = 0; kc < 8; kc++) {
            if (kc < 7) {
                __nv_bfloat16* Bn = ((kc + 1) & 1) ? Bs1 : Bs0;
                for (int i = tid; i < 1024; i += 256) {
                    int r = i >> 3, c = i & 7;
                    cp16(Bn + r * BSTR + c * 8,
                         g_exb + (size_t)(n0 + r) * DIM + (kc + 1) * 64 + c * 8);
                }
                asm volatile("cp.async.commit_group;\n");
                asm volatile("cp.async.wait_group 1;\n");
            } else {
                asm volatile("cp.async.wait_group 0;\n");
            }
            __syncthreads();

            const __nv_bfloat16* Bb =
                ((kc & 1) ? Bs1 : Bs0) + (wn * 32 + g) * BSTR + tg * 2;
            #pragma unroll
            for (int ks = 0; ks < 4; ks++) {
                const int ka = kc * 64 + ks * 16;
                uint32_t afr[4][4], bfr[4][2];
                #pragma unroll
                for (int mi = 0; mi < 4; mi++) {
                    const __nv_bfloat16* p = Ab + mi * 16 * ASTR + ka;
                    afr[mi][0] = *(const uint32_t*)(p);
                    afr[mi][1] = *(const uint32_t*)(p + 8 * ASTR);
                    afr[mi][2] = *(const uint32_t*)(p + 8);
                    afr[mi][3] = *(const uint32_t*)(p + 8 * ASTR + 8);
                }
                #pragma unroll
                for (int ni = 0; ni < 4; ni++) {
                    const __nv_bfloat16* p = Bb + ni * 8 * BSTR + ks * 16;
                    bfr[ni][0] = *(const uint32_t*)(p);
                    bfr[ni][1] = *(const uint32_t*)(p + 8);
                }
                #pragma unroll
                for (int mi = 0; mi < 4; mi++)
                    #pragma unroll
                    for (int ni = 0; ni < 4; ni++)
                        mma16816(acc[mi][ni], afr[mi], bfr[ni]);
            }
            __syncthreads();
        }

        // scale + dump (half tile) + top-8 scan, twice
        #pragma unroll 1
        for (int h = 0; h < 2; h++) {
            __syncthreads();
            if (h_own == h) {
                #pragma unroll
                for (int mi = 0; mi < 4; mi++) {
                    int r0 = wm * 64 + mi * 16 + g;
                    float s0 = rnw[r0], s1 = rnw[r0 + 8];
                    #pragma unroll
                    for (int ni = 0; ni < 4; ni++) {
                        int ct = wn * 32 + ni * 8 + tg * 2;
                        float e0 = rex[ct], e1 = rex[ct + 1];
                        int hc = ct & 63;
                        float2 v01 = make_float2(acc[mi][ni][0] * s0 * e0,
                                                 acc[mi][ni][1] * s0 * e1);
                        float2 v23 = make_float2(acc[mi][ni][2] * s1 * e0,
                                                 acc[mi][ni][3] * s1 * e1);
                        *(float2*)&stage[r0 * STSTR + hc]       = v01;
                        *(float2*)&stage[(r0 + 8) * STSTR + hc] = v23;
                    }
                }
            }
            __syncthreads();
            const int base = n0 + h * 64;
            #pragma unroll 1
            for (int j = par; j < 64; j += 2) {
                float v = stage[rloc * STSTR + j];
                if (v > tv[7]) {
                    tv[7] = v; ti[7] = base + j;
                    #pragma unroll
                    for (int q = 7; q > 0; q--) {
                        if (tv[q] > tv[q - 1]) {
                            float t1 = tv[q]; tv[q] = tv[q - 1]; tv[q - 1] = t1;
                            int   t2 = ti[q]; ti[q] = ti[q - 1]; ti[q - 1] = t2;
                        }
                    }
                }
            }
        }
    }

    size_t pb = (((size_t)(m0 + rloc)) * 16 + (size_t)(split * 2 + par)) * 8;
    #pragma unroll
    for (int q = 0; q < 8; q++) { g_pval[pb + q] = tv[q]; g_pidx[pb + q] = ti[q]; }
}

// ---------------- K3: merge partials, exact fp32 rescore, top-3, aggregate ---
__global__ void k_select(const float* __restrict__ xn, const float* __restrict__ xe) {
    const int row = blockIdx.x;
    const int t = threadIdx.x;   // 128 threads
    __shared__ float sv[128]; __shared__ int si[128];
    __shared__ float xrow[DIM];
    __shared__ int   cidx[8];
    __shared__ float csim[8];
    __shared__ float bsel[4]; __shared__ int bidx[3];

    float v = g_pval[(size_t)row * 128 + t];
    int  ix = g_pidx[(size_t)row * 128 + t];
    bool taken = false;

    for (int sel = 0; sel < 8; ++sel) {
        sv[t] = taken ? -1e30f : v; si[t] = t;
        __syncthreads();
        for (int s = 64; s > 0; s >>= 1) {
            if (t < s) { if (sv[t + s] > sv[t]) { sv[t] = sv[t + s]; si[t] = si[t + s]; } }
            __syncthreads();
        }
        int w = si[0];
        if (t == w) { taken = true; cidx[sel] = ix; }
        __syncthreads();
    }

    #pragma unroll
    for (int q = 0; q < 4; q++)
        xrow[t + q * 128] = xn[(size_t)row * DIM + t + q * 128];
    __syncthreads();

    int wp = t >> 5, ln = t & 31;
    for (int c = wp; c < 8; c += 4) {
        const float* er = xe + (size_t)cidx[c] * DIM;
        float s = 0.f;
        for (int j = ln; j < DIM; j += 32) s += xrow[j] * er[j];
        #pragma unroll
        for (int o = 16; o > 0; o >>= 1) s += __shfl_xor_sync(0xffffffffu, s, o);
        if (ln == 0) csim[c] = s / (g_nnew[row] * g_nex[cidx[c]] + EPSV);
    }
    __syncthreads();

    if (t == 0) {
        float bv[3] = {-1e30f, -1e30f, -1e30f}; int bi[3] = {0, 0, 0};
        for (int c = 0; c < 8; c++) {
            float vv = csim[c]; int ii = cidx[c];
            if (vv > bv[2]) {
                bv[2] = vv; bi[2] = ii;
                if (bv[2] > bv[1]) { float a = bv[1]; bv[1] = bv[2]; bv[2] = a; int b = bi[1]; bi[1] = bi[2]; bi[2] = b; }
                if (bv[1] > bv[0]) { float a = bv[0]; bv[0] = bv[1]; bv[1] = a; int b = bi[0]; bi[0] = bi[1]; bi[1] = b; }
            }
        }
        bsel[0] = bv[0]; bsel[1] = bv[1]; bsel[2] = bv[2];
        bsel[3] = bv[0] + bv[1] + bv[2];
        bidx[0] = bi[0]; bidx[1] = bi[1]; bidx[2] = bi[2];
    }
    __syncthreads();

    float w0 = bsel[0], w1 = bsel[1], w2 = bsel[2], ws = bsel[3];
    const float* e0 = xe + (size_t)bidx[0] * DIM;
    const float* e1 = xe + (size_t)bidx[1] * DIM;
    const float* e2 = xe + (size_t)bidx[2] * DIM;
    #pragma unroll
    for (int q = 0; q < 4; q++) {
        int e = t + q * 128;
        g_agg[(size_t)row * DIM + e] = (w0 * e0[e] + w1 * e1[e] + w2 * e2[e]) / ws;
    }
}

// ---------------- K4/K5: exact fp32 GEMM  Y = X * W^T + b --------------------
__global__ void __launch_bounds__(256) k_gemm(const float* __restrict__ W,
                                              const float* __restrict__ bias,
                                              float* __restrict__ outp, int layer) {
    const float* X = (layer == 0) ? g_agg : g_hbuf;
    float* Y = (layer == 0) ? g_hbuf : outp;

    __shared__ float Xs[32 * 68];
    __shared__ float Ws[32 * 68];
    const int bm = blockIdx.x * 64, bn = blockIdx.y * 64;
    const int t = threadIdx.x, tx = t & 15, ty = t >> 4;
    float acc[4][4];
    #pragma unroll
    for (int i = 0; i < 4; i++)
        #pragma unroll
        for (int j = 0; j < 4; j++) acc[i][j] = 0.f;

    for (int k0 = 0; k0 < DIM; k0 += 32) {
        #pragma unroll
        for (int q = 0; q < 8; q++) {
            int i = t + q * 256;
            int rr = i >> 5, cc = i & 31;
            Xs[cc * 68 + rr] = X[(size_t)(bm + rr) * DIM + k0 + cc];
            Ws[cc * 68 + rr] = W[(size_t)(bn + rr) * DIM + k0 + cc];
        }
        __syncthreads();
        #pragma unroll
        for (int k = 0; k < 32; k++) {
            float4 a  = *(const float4*)&Xs[k * 68 + ty * 4];
            float4 bb = *(const float4*)&Ws[k * 68 + tx * 4];
            float av[4] = {a.x, a.y, a.z, a.w};
            float bv[4] = {bb.x, bb.y, bb.z, bb.w};
            #pragma unroll
            for (int i = 0; i < 4; i++)
                #pragma unroll
                for (int j = 0; j < 4; j++) acc[i][j] += av[i] * bv[j];
        }
        __syncthreads();
    }
    float4 bb = *(const float4*)&bias[bn + tx * 4];
    float bvec[4] = {bb.x, bb.y, bb.z, bb.w};
    #pragma unroll
    for (int i = 0; i < 4; i++) {
        int m = bm + ty * 4 + i;
        float4 o;
        o.x = acc[i][0] + bvec[0]; o.y = acc[i][1] + bvec[1];
        o.z = acc[i][2] + bvec[2]; o.w = acc[i][3] + bvec[3];
        *(float4*)&Y[(size_t)m * DIM + bn + tx * 4] = o;
    }
}

// ---------------- launch ------------------------------------------------------
extern "C" void kernel_launch(void* const* d_in, const int* in_sizes, int n_in,
                              void* d_out, int out_size) {
    (void)in_sizes; (void)n_in; (void)out_size;
    const float* xn = (const float*)d_in[0];
    const float* xe = (const float*)d_in[1];
    const float* fw = (const float*)d_in[2];
    const float* fb = (const float*)d_in[3];
    const float* ow = (const float*)d_in[4];
    const float* ob = (const float*)d_in[5];
    float* out = (float*)d_out;

    k_norm_convert<<<N_NEW + N_EXIST, 128>>>(xn, xe);

    cudaFuncSetAttribute(k_sim_topk, cudaFuncAttributeMaxDynamicSharedMemorySize, SMEM_K2);
    k_sim_topk<<<dim3(N_NEW / MT, NSPLIT), 256, SMEM_K2>>>();

    k_select<<<N_NEW, 128>>>(xn, xe);

    k_gemm<<<dim3(N_NEW / 64, DIM / 64), 256>>>(fw, fb, nullptr, 0);
    k_gemm<<<dim3(N_NEW / 64, DIM / 64), 256>>>(ow, ob, out, 1);
}

// round 6
// speedup vs baseline: 1.0724x; 1.0724x over previous
#include <cuda_runtime.h>
#include <cuda_bf16.h>
#include <cstdint>

#define N_NEW   8192
#define N_EXIST 32768
#define DIM     512
#define EPSV    1e-8f

// ---------------- device scratch (static; no allocation allowed) -------------
__device__ __nv_bfloat16 g_newb[(size_t)N_NEW * DIM];      // 8 MB
__device__ __nv_bfloat16 g_exb[(size_t)N_EXIST * DIM];     // 32 MB
__device__ float g_nnew[N_NEW];
__device__ float g_rnew[N_NEW];
__device__ float g_nex[N_EXIST];
__device__ float g_rex[N_EXIST];
__device__ float g_pval[(size_t)N_NEW * 128];              // 16 partial top-8 sets / row
__device__ int   g_pidx[(size_t)N_NEW * 128];
__device__ float g_agg[(size_t)N_NEW * DIM];               // 16 MB
__device__ float g_hbuf[(size_t)N_NEW * DIM];              // 16 MB

// ---------------- helpers -----------------------------------------------------
__device__ __forceinline__ void cp16(void* smem, const void* gptr) {
    unsigned s = (unsigned)__cvta_generic_to_shared(smem);
    asm volatile("cp.async.cg.shared.global [%0],[%1],16;\n" :: "r"(s), "l"(gptr));
}
__device__ __forceinline__ void mma16816(float* c, const uint32_t* a, const uint32_t* b) {
    asm volatile(
        "mma.sync.aligned.m16n8k16.row.col.f32.bf16.bf16.f32 "
        "{%0,%1,%2,%3},{%4,%5,%6,%7},{%8,%9},{%0,%1,%2,%3};"
        : "+f"(c[0]), "+f"(c[1]), "+f"(c[2]), "+f"(c[3])
        : "r"(a[0]), "r"(a[1]), "r"(a[2]), "r"(a[3]), "r"(b[0]), "r"(b[1]));
}
__device__ __forceinline__ void ldsm4(uint32_t* r, uint32_t addr) {
    asm volatile("ldmatrix.sync.aligned.m8n8.x4.shared.b16 {%0,%1,%2,%3}, [%4];"
                 : "=r"(r[0]), "=r"(r[1]), "=r"(r[2]), "=r"(r[3]) : "r"(addr));
}

// ---------------- K1: norms + bf16 conversion --------------------------------
__global__ void k_norm_convert(const float* __restrict__ xn,
                               const float* __restrict__ xe) {
    int row = blockIdx.x;
    int t   = threadIdx.x;
    bool isnew = row < N_NEW;
    int r = isnew ? row : row - N_NEW;
    const float* src = isnew ? xn + (size_t)r * DIM : xe + (size_t)r * DIM;
    __nv_bfloat16* dst = isnew ? g_newb + (size_t)r * DIM : g_exb + (size_t)r * DIM;

    float4 v = reinterpret_cast<const float4*>(src)[t];
    float s = v.x * v.x + v.y * v.y + v.z * v.z + v.w * v.w;

    __nv_bfloat162 p0, p1;
    p0.x = __float2bfloat16(v.x); p0.y = __float2bfloat16(v.y);
    p1.x = __float2bfloat16(v.z); p1.y = __float2bfloat16(v.w);
    reinterpret_cast<__nv_bfloat162*>(dst)[t * 2]     = p0;
    reinterpret_cast<__nv_bfloat162*>(dst)[t * 2 + 1] = p1;

    #pragma unroll
    for (int o = 16; o > 0; o >>= 1) s += __shfl_xor_sync(0xffffffffu, s, o);
    __shared__ float red[4];
    if ((t & 31) == 0) red[t >> 5] = s;
    __syncthreads();
    if (t == 0) {
        float n = sqrtf(red[0] + red[1] + red[2] + red[3]);
        if (isnew) { g_nnew[r] = n; g_rnew[r] = 1.0f / n; }
        else       { g_nex[r]  = n; g_rex[r]  = 1.0f / n; }
    }
}

// ---------------- K2: mma.sync sim GEMM (ldmatrix feed) + partial top-8 ------
#define MT 128
#define NT 128
#define NSPLIT 8
#define NITER (N_EXIST / (NSPLIT * NT))       // 32
#define NCHUNK (NITER * 4)                    // 128 k-chunks total (k=128 each)
#define STSTR 65

#define SM_A     0                            // 128 x 512 bf16 swizzled: 131072 B
#define SM_B     131072                       // 2 x (128 x 128 bf16) = 2 x 32768
#define SM_STAGE 196608                       // 128 x 65 floats = 33280
#define SM_RNW   229888                       // 128 floats
#define SM_REX   230400                       // 128 floats
#define SMEM_K2  230912                       // <= 232448 opt-in cap

// A: row r (0..127), c16 = 16B unit along K (0..63): XOR-swizzle low 3 bits
__device__ __forceinline__ int swA(int r, int c16) {
    return r * 1024 + ((c16 ^ (r & 7)) << 4);
}
// B chunk: row r (0..127), c16 (0..15)
__device__ __forceinline__ int swB(int r, int c16) {
    return r * 256 + ((c16 ^ (r & 7)) << 4);
}

__global__ void __launch_bounds__(256, 1) k_sim_topk() {
    extern __shared__ unsigned char sraw[];
    const uint32_t sb = (uint32_t)__cvta_generic_to_shared(sraw);
    float* stage = (float*)(sraw + SM_STAGE);
    float* rnw   = (float*)(sraw + SM_RNW);
    float* rex_s = (float*)(sraw + SM_REX);

    const int tid  = threadIdx.x;
    const int warp = tid >> 5, lane = tid & 31;
    const int wm = warp & 1, wn = warp >> 1;       // 2 x 4 warp grid, tile 64x32
    const int g  = lane >> 2, tg = lane & 3;
    const int t4 = lane >> 3, l7 = lane & 7;       // ldmatrix addressing
    const int m0    = blockIdx.x * MT;
    const int split = blockIdx.y;
    const int h_own = wn >> 1;
    const int rloc = tid & 127, par = tid >> 7;

    // per-thread ldmatrix row bases (row & 7 == l7 for all fragment rows)
    uint32_t aBase[4];
    #pragma unroll
    for (int mi = 0; mi < 4; mi++) {
        int rowA = wm * 64 + mi * 16 + (t4 & 1) * 8 + l7;
        aBase[mi] = sb + SM_A + rowA * 1024;
    }
    uint32_t bRow[2];
    #pragma unroll
    for (int nia = 0; nia < 2; nia++) {
        int rowB = wn * 32 + nia * 16 + (t4 >> 1) * 8 + l7;
        bRow[nia] = rowB * 256;
    }
    const int aC16base = (t4 >> 1);      // +0/+1 16B unit (k low/high 8)
    const int bC16base = (t4 & 1);

    if (tid < 128) rnw[tid] = g_rnew[m0 + tid];

    // A tile load: 8192 16B units -> swizzled
    #pragma unroll 8
    for (int q = 0; q < 32; q++) {
        int u = tid + q * 256;
        int r = u >> 6, c16 = u & 63;
        cp16(sraw + SM_A + swA(r, c16), g_newb + (size_t)(m0 + r) * DIM + c16 * 8);
    }
    asm volatile("cp.async.commit_group;\n");

    // prologue: chunks 0,1
    #pragma unroll
    for (int pc = 0; pc < 2; pc++) {
        const int n0 = split * (NT * NITER);
        #pragma unroll
        for (int q = 0; q < 8; q++) {
            int u = tid + q * 256;
            int r = u >> 4, c16 = u & 15;
            cp16(sraw + SM_B + pc * 32768 + swB(r, c16),
                 g_exb + (size_t)(n0 + r) * DIM + pc * 128 + c16 * 8);
        }
        asm volatile("cp.async.commit_group;\n");
    }

    float tv[8]; int ti[8];
    #pragma unroll
    for (int q = 0; q < 8; q++) { tv[q] = -1e30f; ti[q] = 0; }

    int gc = 0;
    #pragma unroll 1
    for (int it = 0; it < NITER; ++it) {
        const int n0 = split * (NT * NITER) + it * NT;
        if (tid < NT) rex_s[tid] = g_rex[n0 + tid];

        float acc[4][4][4];
        #pragma unroll
        for (int a = 0; a < 4; a++)
            #pragma unroll
            for (int b = 0; b < 4; b++)
                #pragma unroll
                for (int c = 0; c < 4; c++) acc[a][b][c] = 0.f;

        #pragma unroll 1
        for (int kc = 0; kc < 4; kc++, gc++) {
            if (gc + 1 < NCHUNK) asm volatile("cp.async.wait_group 1;\n");
            else                 asm volatile("cp.async.wait_group 0;\n");
            __syncthreads();

            const uint32_t bBuf = sb + SM_B + (gc & 1) * 32768;
            #pragma unroll
            for (int ks = 0; ks < 8; ks++) {
                uint32_t afr[4][4], bfr[2][4];
                const int ac16 = kc * 16 + ks * 2 + aC16base;
                #pragma unroll
                for (int mi = 0; mi < 4; mi++)
                    ldsm4(afr[mi], aBase[mi] + (((uint32_t)(ac16 ^ l7)) << 4));
                const int bc16 = ks * 2 + bC16base;
                #pragma unroll
                for (int nia = 0; nia < 2; nia++)
                    ldsm4(bfr[nia], bBuf + bRow[nia] + (((uint32_t)(bc16 ^ l7)) << 4));
                #pragma unroll
                for (int mi = 0; mi < 4; mi++) {
                    mma16816(acc[mi][0], afr[mi], bfr[0]);
                    mma16816(acc[mi][1], afr[mi], bfr[0] + 2);
                    mma16816(acc[mi][2], afr[mi], bfr[1]);
                    mma16816(acc[mi][3], afr[mi], bfr[1] + 2);
                }
            }
            __syncthreads();

            if (gc + 2 < NCHUNK) {
                const int ng  = gc + 2;
                const int nit = ng >> 2, nkc = ng & 3;
                const int nn0 = split * (NT * NITER) + nit * NT;
                #pragma unroll
                for (int q = 0; q < 8; q++) {
                    int u = tid + q * 256;
                    int r = u >> 4, c16 = u & 15;
                    cp16(sraw + SM_B + (ng & 1) * 32768 + swB(r, c16),
                         g_exb + (size_t)(nn0 + r) * DIM + nkc * 128 + c16 * 8);
                }
                asm volatile("cp.async.commit_group;\n");
            }
        }

        // scale + stage half tile + top-8 scan, twice
        #pragma unroll 1
        for (int h = 0; h < 2; h++) {
            __syncthreads();
            if (h_own == h) {
                #pragma unroll
                for (int mi = 0; mi < 4; mi++) {
                    int r0 = wm * 64 + mi * 16 + g;
                    float s0 = rnw[r0], s1 = rnw[r0 + 8];
                    #pragma unroll
                    for (int ni = 0; ni < 4; ni++) {
                        int ct = wn * 32 + ni * 8 + tg * 2;
                        float e0 = rex_s[ct], e1 = rex_s[ct + 1];
                        int hc = ct & 63;
                        stage[r0 * STSTR + hc]           = acc[mi][ni][0] * s0 * e0;
                        stage[r0 * STSTR + hc + 1]       = acc[mi][ni][1] * s0 * e1;
                        stage[(r0 + 8) * STSTR + hc]     = acc[mi][ni][2] * s1 * e0;
                        stage[(r0 + 8) * STSTR + hc + 1] = acc[mi][ni][3] * s1 * e1;
                    }
                }
            }
            __syncthreads();
            const int base = n0 + h * 64;
            #pragma unroll 1
            for (int j = par; j < 64; j += 2) {
                float v = stage[rloc * STSTR + j];
                if (v > tv[7]) {
                    tv[7] = v; ti[7] = base + j;
                    #pragma unroll
                    for (int q = 7; q > 0; q--)
                        if (tv[q] > tv[q - 1]) {
                            float a = tv[q]; tv[q] = tv[q - 1]; tv[q - 1] = a;
                            int   b = ti[q]; ti[q] = ti[q - 1]; ti[q - 1] = b;
                        }
                }
            }
        }
    }

    size_t pb = (((size_t)(m0 + rloc)) * 16 + (size_t)(split * 2 + par)) * 8;
    #pragma unroll
    for (int q = 0; q < 8; q++) { g_pval[pb + q] = tv[q]; g_pidx[pb + q] = ti[q]; }
}

// ---------------- K3: merge partials, exact fp32 rescore, top-3, aggregate ---
__global__ void k_select(const float* __restrict__ xn, const float* __restrict__ xe) {
    const int row = blockIdx.x;
    const int t = threadIdx.x;   // 128 threads
    __shared__ float sv[128]; __shared__ int si[128];
    __shared__ float xrow[DIM];
    __shared__ int   cidx[8];
    __shared__ float csim[8];
    __shared__ float bsel[4]; __shared__ int bidx[3];

    float v = g_pval[(size_t)row * 128 + t];
    int  ix = g_pidx[(size_t)row * 128 + t];
    bool taken = false;

    for (int sel = 0; sel < 8; ++sel) {
        sv[t] = taken ? -1e30f : v; si[t] = t;
        __syncthreads();
        for (int s = 64; s > 0; s >>= 1) {
            if (t < s) { if (sv[t + s] > sv[t]) { sv[t] = sv[t + s]; si[t] = si[t + s]; } }
            __syncthreads();
        }
        int w = si[0];
        if (t == w) { taken = true; cidx[sel] = ix; }
        __syncthreads();
    }

    #pragma unroll
    for (int q = 0; q < 4; q++)
        xrow[t + q * 128] = xn[(size_t)row * DIM + t + q * 128];
    __syncthreads();

    int wp = t >> 5, ln = t & 31;
    for (int c = wp; c < 8; c += 4) {
        const float* er = xe + (size_t)cidx[c] * DIM;
        float s = 0.f;
        for (int j = ln; j < DIM; j += 32) s += xrow[j] * er[j];
        #pragma unroll
        for (int o = 16; o > 0; o >>= 1) s += __shfl_xor_sync(0xffffffffu, s, o);
        if (ln == 0) csim[c] = s / (g_nnew[row] * g_nex[cidx[c]] + EPSV);
    }
    __syncthreads();

    if (t == 0) {
        float bv[3] = {-1e30f, -1e30f, -1e30f}; int bi[3] = {0, 0, 0};
        for (int c = 0; c < 8; c++) {
            float vv = csim[c]; int ii = cidx[c];
            if (vv > bv[2]) {
                bv[2] = vv; bi[2] = ii;
                if (bv[2] > bv[1]) { float a = bv[1]; bv[1] = bv[2]; bv[2] = a; int b = bi[1]; bi[1] = bi[2]; bi[2] = b; }
                if (bv[1] > bv[0]) { float a = bv[0]; bv[0] = bv[1]; bv[1] = a; int b = bi[0]; bi[0] = bi[1]; bi[1] = b; }
            }
        }
        bsel[0] = bv[0]; bsel[1] = bv[1]; bsel[2] = bv[2];
        bsel[3] = bv[0] + bv[1] + bv[2];
        bidx[0] = bi[0]; bidx[1] = bi[1]; bidx[2] = bi[2];
    }
    __syncthreads();

    float w0 = bsel[0], w1 = bsel[1], w2 = bsel[2], ws = bsel[3];
    const float* e0 = xe + (size_t)bidx[0] * DIM;
    const float* e1 = xe + (size_t)bidx[1] * DIM;
    const float* e2 = xe + (size_t)bidx[2] * DIM;
    #pragma unroll
    for (int q = 0; q < 4; q++) {
        int e = t + q * 128;
        g_agg[(size_t)row * DIM + e] = (w0 * e0[e] + w1 * e1[e] + w2 * e2[e]) / ws;
    }
}

// ---------------- K4/K5: exact fp32 GEMM  Y = X * W^T + b --------------------
__global__ void __launch_bounds__(256) k_gemm(const float* __restrict__ W,
                                              const float* __restrict__ bias,
                                              float* __restrict__ outp, int layer) {
    const float* X = (layer == 0) ? g_agg : g_hbuf;
    float* Y = (layer == 0) ? g_hbuf : outp;

    __shared__ float Xs[32 * 68];
    __shared__ float Ws[32 * 68];
    const int bm = blockIdx.x * 64, bn = blockIdx.y * 64;
    const int t = threadIdx.x, tx = t & 15, ty = t >> 4;
    float acc[4][4];
    #pragma unroll
    for (int i = 0; i < 4; i++)
        #pragma unroll
        for (int j = 0; j < 4; j++) acc[i][j] = 0.f;

    for (int k0 = 0; k0 < DIM; k0 += 32) {
        #pragma unroll
        for (int q = 0; q < 8; q++) {
            int i = t + q * 256;
            int rr = i >> 5, cc = i & 31;
            Xs[cc * 68 + rr] = X[(size_t)(bm + rr) * DIM + k0 + cc];
            Ws[cc * 68 + rr] = W[(size_t)(bn + rr) * DIM + k0 + cc];
        }
        __syncthreads();
        #pragma unroll
        for (int k = 0; k < 32; k++) {
            float4 a  = *(const float4*)&Xs[k * 68 + ty * 4];
            float4 bb = *(const float4*)&Ws[k * 68 + tx * 4];
            float av[4] = {a.x, a.y, a.z, a.w};
            float bv[4] = {bb.x, bb.y, bb.z, bb.w};
            #pragma unroll
            for (int i = 0; i < 4; i++)
                #pragma unroll
                for (int j = 0; j < 4; j++) acc[i][j] += av[i] * bv[j];
        }
        __syncthreads();
    }
    float4 bb = *(const float4*)&bias[bn + tx * 4];
    float bvec[4] = {bb.x, bb.y, bb.z, bb.w};
    #pragma unroll
    for (int i = 0; i < 4; i++) {
        int m = bm + ty * 4 + i;
        float4 o;
        o.x = acc[i][0] + bvec[0]; o.y = acc[i][1] + bvec[1];
        o.z = acc[i][2] + bvec[2]; o.w = acc[i][3] + bvec[3];
        *(float4*)&Y[(size_t)m * DIM + bn + tx * 4] = o;
    }
}

// ---------------- launch ------------------------------------------------------
extern "C" void kernel_launch(void* const* d_in, const int* in_sizes, int n_in,
                              void* d_out, int out_size) {
    (void)in_sizes; (void)n_in; (void)out_size;
    const float* xn = (const float*)d_in[0];
    const float* xe = (const float*)d_in[1];
    const float* fw = (const float*)d_in[2];
    const float* fb = (const float*)d_in[3];
    const float* ow = (const float*)d_in[4];
    const float* ob = (const float*)d_in[5];
    float* out = (float*)d_out;

    k_norm_convert<<<N_NEW + N_EXIST, 128>>>(xn, xe);

    cudaFuncSetAttribute(k_sim_topk, cudaFuncAttributeMaxDynamicSharedMemorySize, SMEM_K2);
    k_sim_topk<<<dim3(N_NEW / MT, NSPLIT), 256, SMEM_K2>>>();

    k_select<<<N_NEW, 128>>>(xn, xe);

    k_gemm<<<dim3(N_NEW / 64, DIM / 64), 256>>>(fw, fb, nullptr, 0);
    k_gemm<<<dim3(N_NEW / 64, DIM / 64), 256>>>(ow, ob, out, 1);
}

// round 7
// speedup vs baseline: 1.4405x; 1.3432x over previous
#include <cuda_runtime.h>
#include <cuda_bf16.h>
#include <cstdint>

#define N_NEW   8192
#define N_EXIST 32768
#define DIM     512
#define EPSV    1e-8f

// ---------------- device scratch (static; no allocation allowed) -------------
__device__ __nv_bfloat16 g_newb[(size_t)N_NEW * DIM];      // 8 MB
__device__ __nv_bfloat16 g_exb[(size_t)N_EXIST * DIM];     // 32 MB
__device__ float g_nnew[N_NEW];
__device__ float g_rnew[N_NEW];
__device__ float g_nex[N_EXIST];
__device__ float g_rex[N_EXIST];
__device__ float g_pval[(size_t)N_NEW * 384];              // per-row candidates
__device__ int   g_pidx[(size_t)N_NEW * 384];
__device__ float g_agg[(size_t)N_NEW * DIM];               // 16 MB
__device__ float g_hbuf[(size_t)N_NEW * DIM];              // 16 MB

// ---------------- helpers -----------------------------------------------------
__device__ __forceinline__ void cp16(void* smem, const void* gptr) {
    unsigned s = (unsigned)__cvta_generic_to_shared(smem);
    asm volatile("cp.async.cg.shared.global [%0],[%1],16;\n" :: "r"(s), "l"(gptr));
}
__device__ __forceinline__ void mma16816(float* c, const uint32_t* a, const uint32_t* b) {
    asm volatile(
        "mma.sync.aligned.m16n8k16.row.col.f32.bf16.bf16.f32 "
        "{%0,%1,%2,%3},{%4,%5,%6,%7},{%8,%9},{%0,%1,%2,%3};"
        : "+f"(c[0]), "+f"(c[1]), "+f"(c[2]), "+f"(c[3])
        : "r"(a[0]), "r"(a[1]), "r"(a[2]), "r"(a[3]), "r"(b[0]), "r"(b[1]));
}
__device__ __forceinline__ void ldsm4(uint32_t* r, uint32_t addr) {
    asm volatile("ldmatrix.sync.aligned.m8n8.x4.shared.b16 {%0,%1,%2,%3}, [%4];"
                 : "=r"(r[0]), "=r"(r[1]), "=r"(r[2]), "=r"(r[3]) : "r"(addr));
}

// ---------------- K1: norms + bf16 conversion --------------------------------
__global__ void k_norm_convert(const float* __restrict__ xn,
                               const float* __restrict__ xe) {
    int row = blockIdx.x;
    int t   = threadIdx.x;
    bool isnew = row < N_NEW;
    int r = isnew ? row : row - N_NEW;
    const float* src = isnew ? xn + (size_t)r * DIM : xe + (size_t)r * DIM;
    __nv_bfloat16* dst = isnew ? g_newb + (size_t)r * DIM : g_exb + (size_t)r * DIM;

    float4 v = reinterpret_cast<const float4*>(src)[t];
    float s = v.x * v.x + v.y * v.y + v.z * v.z + v.w * v.w;

    __nv_bfloat162 p0, p1;
    p0.x = __float2bfloat16(v.x); p0.y = __float2bfloat16(v.y);
    p1.x = __float2bfloat16(v.z); p1.y = __float2bfloat16(v.w);
    reinterpret_cast<__nv_bfloat162*>(dst)[t * 2]     = p0;
    reinterpret_cast<__nv_bfloat162*>(dst)[t * 2 + 1] = p1;

    #pragma unroll
    for (int o = 16; o > 0; o >>= 1) s += __shfl_xor_sync(0xffffffffu, s, o);
    __shared__ float red[4];
    if ((t & 31) == 0) red[t >> 5] = s;
    __syncthreads();
    if (t == 0) {
        float n = sqrtf(red[0] + red[1] + red[2] + red[3]);
        if (isnew) { g_nnew[r] = n; g_rnew[r] = 1.0f / n; }
        else       { g_nex[r]  = n; g_rex[r]  = 1.0f / n; }
    }
}

// ---------------- K2: mma.sync sim GEMM + in-register per-stream top-3 -------
#define MT 128
#define NT 128
#define NSPLIT 8
#define NITER (N_EXIST / (NSPLIT * NT))       // 32
#define NCHUNK (NITER * 4)                    // 128 k-chunks (k=128 each)

#define SM_A     0                            // 128 x 512 bf16 swizzled: 131072 B
#define SM_B     131072                       // 3 x (128 x 128 bf16) = 3 x 32768
#define SM_REX   229376                       // 128 floats
#define SMEM_K2  229888

// A: row r (0..127), c16 = 16B unit along K (0..63): XOR-swizzle low 3 bits
__device__ __forceinline__ int swA(int r, int c16) {
    return r * 1024 + ((c16 ^ (r & 7)) << 4);
}
// B chunk: row r (0..127), c16 (0..15)
__device__ __forceinline__ int swB(int r, int c16) {
    return r * 256 + ((c16 ^ (r & 7)) << 4);
}

// top-3 insertion on constant-indexed register arrays
#define TOP3_UPD(s, vv, cc)                                          \
    do {                                                             \
        float _v = (vv);                                             \
        if (_v > tv3[s][2]) {                                        \
            if (_v > tv3[s][0]) {                                    \
                tv3[s][2] = tv3[s][1]; ti3[s][2] = ti3[s][1];        \
                tv3[s][1] = tv3[s][0]; ti3[s][1] = ti3[s][0];        \
                tv3[s][0] = _v;        ti3[s][0] = (cc);             \
            } else if (_v > tv3[s][1]) {                             \
                tv3[s][2] = tv3[s][1]; ti3[s][2] = ti3[s][1];        \
                tv3[s][1] = _v;        ti3[s][1] = (cc);             \
            } else {                                                 \
                tv3[s][2] = _v;        ti3[s][2] = (cc);             \
            }                                                        \
        }                                                            \
    } while (0)

__global__ void __launch_bounds__(256, 1) k_sim_topk() {
    extern __shared__ unsigned char sraw[];
    const uint32_t sb = (uint32_t)__cvta_generic_to_shared(sraw);
    float* rex_s = (float*)(sraw + SM_REX);

    const int tid  = threadIdx.x;
    const int warp = tid >> 5, lane = tid & 31;
    const int wm = warp & 1, wn = warp >> 1;       // 2 x 4 warp grid, tile 64x32
    const int g  = lane >> 2, tg = lane & 3;
    const int t4 = lane >> 3, l7 = lane & 7;       // ldmatrix addressing
    const int m0    = blockIdx.x * MT;
    const int split = blockIdx.y;

    // per-thread ldmatrix row bases
    uint32_t aBase[4];
    #pragma unroll
    for (int mi = 0; mi < 4; mi++) {
        int rowA = wm * 64 + mi * 16 + (t4 & 1) * 8 + l7;
        aBase[mi] = sb + SM_A + rowA * 1024;
    }
    uint32_t bRow[2];
    #pragma unroll
    for (int nia = 0; nia < 2; nia++) {
        int rowB = wn * 32 + nia * 16 + (t4 >> 1) * 8 + l7;
        bRow[nia] = rowB * 256;
    }
    const int aC16base = (t4 >> 1);
    const int bC16base = (t4 & 1);

    // per-thread row norms (8 owned rows)
    float rn[8];
    #pragma unroll
    for (int s = 0; s < 8; s++)
        rn[s] = g_rnew[m0 + wm * 64 + (s >> 1) * 16 + (s & 1) * 8 + g];

    // A tile load: 8192 16B units -> swizzled
    #pragma unroll 8
    for (int q = 0; q < 32; q++) {
        int u = tid + q * 256;
        int r = u >> 6, c16 = u & 63;
        cp16(sraw + SM_A + swA(r, c16), g_newb + (size_t)(m0 + r) * DIM + c16 * 8);
    }
    asm volatile("cp.async.commit_group;\n");

    // prologue: B chunks 0,1
    #pragma unroll
    for (int pc = 0; pc < 2; pc++) {
        const int n0 = split * (NT * NITER);
        #pragma unroll
        for (int q = 0; q < 8; q++) {
            int u = tid + q * 256;
            int r = u >> 4, c16 = u & 15;
            cp16(sraw + SM_B + pc * 32768 + swB(r, c16),
                 g_exb + (size_t)(n0 + r) * DIM + pc * 128 + c16 * 8);
        }
        asm volatile("cp.async.commit_group;\n");
    }

    float tv3[8][3]; int ti3[8][3];
    #pragma unroll
    for (int s = 0; s < 8; s++)
        #pragma unroll
        for (int q = 0; q < 3; q++) { tv3[s][q] = -1e30f; ti3[s][q] = 0; }

    int gc = 0;
    #pragma unroll 1
    for (int it = 0; it < NITER; ++it) {
        const int n0 = split * (NT * NITER) + it * NT;

        float acc[4][4][4];
        #pragma unroll
        for (int a = 0; a < 4; a++)
            #pragma unroll
            for (int b = 0; b < 4; b++)
                #pragma unroll
                for (int c = 0; c < 4; c++) acc[a][b][c] = 0.f;

        #pragma unroll 1
        for (int kc = 0; kc < 4; kc++, gc++) {
            if (gc < NCHUNK - 1) asm volatile("cp.async.wait_group 1;\n");
            else                 asm volatile("cp.async.wait_group 0;\n");
            __syncthreads();

            if (kc == 0 && tid < NT) rex_s[tid] = g_rex[n0 + tid];

            // prefetch chunk gc+2 into buffer freed by chunk gc-1
            if (gc + 2 < NCHUNK) {
                const int ng  = gc + 2;
                const int nit = ng >> 2, nkc = ng & 3;
                const int nn0 = split * (NT * NITER) + nit * NT;
                #pragma unroll
                for (int q = 0; q < 8; q++) {
                    int u = tid + q * 256;
                    int r = u >> 4, c16 = u & 15;
                    cp16(sraw + SM_B + (ng % 3) * 32768 + swB(r, c16),
                         g_exb + (size_t)(nn0 + r) * DIM + nkc * 128 + c16 * 8);
                }
                asm volatile("cp.async.commit_group;\n");
            }

            const uint32_t bBuf = sb + SM_B + (gc % 3) * 32768;
            #pragma unroll
            for (int ks = 0; ks < 8; ks++) {
                uint32_t afr[4][4], bfr[2][4];
                const int ac16 = kc * 16 + ks * 2 + aC16base;
                #pragma unroll
                for (int mi = 0; mi < 4; mi++)
                    ldsm4(afr[mi], aBase[mi] + (((uint32_t)(ac16 ^ l7)) << 4));
                const int bc16 = ks * 2 + bC16base;
                #pragma unroll
                for (int nia = 0; nia < 2; nia++)
                    ldsm4(bfr[nia], bBuf + bRow[nia] + (((uint32_t)(bc16 ^ l7)) << 4));
                #pragma unroll
                for (int mi = 0; mi < 4; mi++) {
                    mma16816(acc[mi][0], afr[mi], bfr[0]);
                    mma16816(acc[mi][1], afr[mi], bfr[0] + 2);
                    mma16816(acc[mi][2], afr[mi], bfr[1]);
                    mma16816(acc[mi][3], afr[mi], bfr[1] + 2);
                }
            }
        }

        // in-register epilogue: scale + per-stream top-3 (no syncs, no staging)
        #pragma unroll
        for (int ni = 0; ni < 4; ni++) {
            const int ct = wn * 32 + ni * 8 + tg * 2;
            const float e0 = rex_s[ct], e1 = rex_s[ct + 1];
            const int c0 = n0 + ct, c1 = c0 + 1;
            #pragma unroll
            for (int mi = 0; mi < 4; mi++) {
                TOP3_UPD(2 * mi,     acc[mi][ni][0] * rn[2 * mi] * e0,     c0);
                TOP3_UPD(2 * mi,     acc[mi][ni][1] * rn[2 * mi] * e1,     c1);
                TOP3_UPD(2 * mi + 1, acc[mi][ni][2] * rn[2 * mi + 1] * e0, c0);
                TOP3_UPD(2 * mi + 1, acc[mi][ni][3] * rn[2 * mi + 1] * e1, c1);
            }
        }
    }

    // write per-stream top-3 candidates: row-major, 384 per row
    const int cth = wn * 4 + tg;                     // 0..15 column-thread id
    #pragma unroll
    for (int s = 0; s < 8; s++) {
        int row = m0 + wm * 64 + (s >> 1) * 16 + (s & 1) * 8 + g;
        size_t base = ((size_t)row * NSPLIT + split) * 48 + cth * 3;
        #pragma unroll
        for (int q = 0; q < 3; q++) {
            g_pval[base + q] = tv3[s][q];
            g_pidx[base + q] = ti3[s][q];
        }
    }
}

// ---------------- K3: merge 384 candidates, exact rescore, top-3, aggregate --
__global__ void k_select(const float* __restrict__ xn, const float* __restrict__ xe) {
    const int row = blockIdx.x;
    const int t = threadIdx.x;   // 128 threads
    __shared__ float sv[128]; __shared__ int si[128];
    __shared__ float xrow[DIM];
    __shared__ int   cidx[8];
    __shared__ float csim[8];
    __shared__ float bsel[4]; __shared__ int bidx[3];

    float cv[3]; int ci[3]; bool tk[3] = {false, false, false};
    {
        size_t base = (size_t)row * 384 + t * 3;
        #pragma unroll
        for (int q = 0; q < 3; q++) { cv[q] = g_pval[base + q]; ci[q] = g_pidx[base + q]; }
    }

    for (int sel = 0; sel < 8; ++sel) {
        float lv = -1e30f; int lq = 0;
        #pragma unroll
        for (int q = 0; q < 3; q++)
            if (!tk[q] && cv[q] > lv) { lv = cv[q]; lq = q; }
        sv[t] = lv; si[t] = t * 4 + lq;
        __syncthreads();
        for (int s = 64; s > 0; s >>= 1) {
            if (t < s) { if (sv[t + s] > sv[t]) { sv[t] = sv[t + s]; si[t] = si[t + s]; } }
            __syncthreads();
        }
        int w = si[0];
        if (t == (w >> 2)) { tk[w & 3] = true; cidx[sel] = ci[w & 3]; }
        __syncthreads();
    }

    #pragma unroll
    for (int q = 0; q < 4; q++)
        xrow[t + q * 128] = xn[(size_t)row * DIM + t + q * 128];
    __syncthreads();

    int wp = t >> 5, ln = t & 31;
    for (int c = wp; c < 8; c += 4) {
        const float* er = xe + (size_t)cidx[c] * DIM;
        float s = 0.f;
        for (int j = ln; j < DIM; j += 32) s += xrow[j] * er[j];
        #pragma unroll
        for (int o = 16; o > 0; o >>= 1) s += __shfl_xor_sync(0xffffffffu, s, o);
        if (ln == 0) csim[c] = s / (g_nnew[row] * g_nex[cidx[c]] + EPSV);
    }
    __syncthreads();

    if (t == 0) {
        float bv[3] = {-1e30f, -1e30f, -1e30f}; int bi[3] = {0, 0, 0};
        for (int c = 0; c < 8; c++) {
            float vv = csim[c]; int ii = cidx[c];
            if (vv > bv[2]) {
                bv[2] = vv; bi[2] = ii;
                if (bv[2] > bv[1]) { float a = bv[1]; bv[1] = bv[2]; bv[2] = a; int b = bi[1]; bi[1] = bi[2]; bi[2] = b; }
                if (bv[1] > bv[0]) { float a = bv[0]; bv[0] = bv[1]; bv[1] = a; int b = bi[0]; bi[0] = bi[1]; bi[1] = b; }
            }
        }
        bsel[0] = bv[0]; bsel[1] = bv[1]; bsel[2] = bv[2];
        bsel[3] = bv[0] + bv[1] + bv[2];
        bidx[0] = bi[0]; bidx[1] = bi[1]; bidx[2] = bi[2];
    }
    __syncthreads();

    float w0 = bsel[0], w1 = bsel[1], w2 = bsel[2], ws = bsel[3];
    const float* e0 = xe + (size_t)bidx[0] * DIM;
    const float* e1 = xe + (size_t)bidx[1] * DIM;
    const float* e2 = xe + (size_t)bidx[2] * DIM;
    #pragma unroll
    for (int q = 0; q < 4; q++) {
        int e = t + q * 128;
        g_agg[(size_t)row * DIM + e] = (w0 * e0[e] + w1 * e1[e] + w2 * e2[e]) / ws;
    }
}

// ---------------- K4/K5: exact fp32 GEMM  Y = X * W^T + b --------------------
__global__ void __launch_bounds__(256) k_gemm(const float* __restrict__ W,
                                              const float* __restrict__ bias,
                                              float* __restrict__ outp, int layer) {
    const float* X = (layer == 0) ? g_agg : g_hbuf;
    float* Y = (layer == 0) ? g_hbuf : outp;

    __shared__ float Xs[32 * 68];
    __shared__ float Ws[32 * 68];
    const int bm = blockIdx.x * 64, bn = blockIdx.y * 64;
    const int t = threadIdx.x, tx = t & 15, ty = t >> 4;
    float acc[4][4];
    #pragma unroll
    for (int i = 0; i < 4; i++)
        #pragma unroll
        for (int j = 0; j < 4; j++) acc[i][j] = 0.f;

    for (int k0 = 0; k0 < DIM; k0 += 32) {
        #pragma unroll
        for (int q = 0; q < 8; q++) {
            int i = t + q * 256;
            int rr = i >> 5, cc = i & 31;
            Xs[cc * 68 + rr] = X[(size_t)(bm + rr) * DIM + k0 + cc];
            Ws[cc * 68 + rr] = W[(size_t)(bn + rr) * DIM + k0 + cc];
        }
        __syncthreads();
        #pragma unroll
        for (int k = 0; k < 32; k++) {
            float4 a  = *(const float4*)&Xs[k * 68 + ty * 4];
            float4 bb = *(const float4*)&Ws[k * 68 + tx * 4];
            float av[4] = {a.x, a.y, a.z, a.w};
            float bv[4] = {bb.x, bb.y, bb.z, bb.w};
            #pragma unroll
            for (int i = 0; i < 4; i++)
                #pragma unroll
                for (int j = 0; j < 4; j++) acc[i][j] += av[i] * bv[j];
        }
        __syncthreads();
    }
    float4 bb = *(const float4*)&bias[bn + tx * 4];
    float bvec[4] = {bb.x, bb.y, bb.z, bb.w};
    #pragma unroll
    for (int i = 0; i < 4; i++) {
        int m = bm + ty * 4 + i;
        float4 o;
        o.x = acc[i][0] + bvec[0]; o.y = acc[i][1] + bvec[1];
        o.z = acc[i][2] + bvec[2]; o.w = acc[i][3] + bvec[3];
        *(float4*)&Y[(size_t)m * DIM + bn + tx * 4] = o;
    }
}

// ---------------- launch ------------------------------------------------------
extern "C" void kernel_launch(void* const* d_in, const int* in_sizes, int n_in,
                              void* d_out, int out_size) {
    (void)in_sizes; (void)n_in; (void)out_size;
    const float* xn = (const float*)d_in[0];
    const float* xe = (const float*)d_in[1];
    const float* fw = (const float*)d_in[2];
    const float* fb = (const float*)d_in[3];
    const float* ow = (const float*)d_in[4];
    const float* ob = (const float*)d_in[5];
    float* out = (float*)d_out;

    k_norm_convert<<<N_NEW + N_EXIST, 128>>>(xn, xe);

    cudaFuncSetAttribute(k_sim_topk, cudaFuncAttributeMaxDynamicSharedMemorySize, SMEM_K2);
    k_sim_topk<<<dim3(N_NEW / MT, NSPLIT), 256, SMEM_K2>>>();

    k_select<<<N_NEW, 128>>>(xn, xe);

    k_gemm<<<dim3(N_NEW / 64, DIM / 64), 256>>>(fw, fb, nullptr, 0);
    k_gemm<<<dim3(N_NEW / 64, DIM / 64), 256>>>(ow, ob, out, 1);
}

// round 12
// speedup vs baseline: 1.5625x; 1.0847x over previous
#include <cuda_runtime.h>
#include <cuda_bf16.h>
#include <cstdint>

#define N_NEW   8192
#define N_EXIST 32768
#define DIM     512
#define EPSV    1e-8f

// ---------------- device scratch (static; no allocation allowed) -------------
__device__ __nv_bfloat16 g_newb[(size_t)N_NEW * DIM];      // 8 MB
__device__ __nv_bfloat16 g_exb[(size_t)N_EXIST * DIM];     // 32 MB
__device__ float g_nnew[N_NEW];
__device__ float g_rnew[N_NEW];
__device__ float g_nex[N_EXIST];
__device__ float g_rex[N_EXIST];
__device__ float g_pval[(size_t)N_NEW * 384];              // per-row candidates
__device__ int   g_pidx[(size_t)N_NEW * 384];
__device__ float g_agg[(size_t)N_NEW * DIM];               // 16 MB
__device__ float g_W[DIM * DIM];                           // fused weight om@fc
__device__ float g_c[DIM];                                 // fused bias om@fb + ob

// ---------------- helpers -----------------------------------------------------
__device__ __forceinline__ void cp16(void* smem, const void* gptr) {
    unsigned s = (unsigned)__cvta_generic_to_shared(smem);
    asm volatile("cp.async.cg.shared.global [%0],[%1],16;\n" :: "r"(s), "l"(gptr));
}
__device__ __forceinline__ void mma16816(float* c, const uint32_t* a, const uint32_t* b) {
    asm volatile(
        "mma.sync.aligned.m16n8k16.row.col.f32.bf16.bf16.f32 "
        "{%0,%1,%2,%3},{%4,%5,%6,%7},{%8,%9},{%0,%1,%2,%3};"
        : "+f"(c[0]), "+f"(c[1]), "+f"(c[2]), "+f"(c[3])
        : "r"(a[0]), "r"(a[1]), "r"(a[2]), "r"(a[3]), "r"(b[0]), "r"(b[1]));
}
__device__ __forceinline__ void ldsm4(uint32_t* r, uint32_t addr) {
    asm volatile("ldmatrix.sync.aligned.m8n8.x4.shared.b16 {%0,%1,%2,%3}, [%4];"
                 : "=r"(r[0]), "=r"(r[1]), "=r"(r[2]), "=r"(r[3]) : "r"(addr));
}

// ---------------- K1: norms + bf16 conversion --------------------------------
__global__ void k_norm_convert(const float* __restrict__ xn,
                               const float* __restrict__ xe) {
    int row = blockIdx.x;
    int t   = threadIdx.x;
    bool isnew = row < N_NEW;
    int r = isnew ? row : row - N_NEW;
    const float* src = isnew ? xn + (size_t)r * DIM : xe + (size_t)r * DIM;
    __nv_bfloat16* dst = isnew ? g_newb + (size_t)r * DIM : g_exb + (size_t)r * DIM;

    float4 v = reinterpret_cast<const float4*>(src)[t];
    float s = v.x * v.x + v.y * v.y + v.z * v.z + v.w * v.w;

    __nv_bfloat162 p0, p1;
    p0.x = __float2bfloat16(v.x); p0.y = __float2bfloat16(v.y);
    p1.x = __float2bfloat16(v.z); p1.y = __float2bfloat16(v.w);
    reinterpret_cast<__nv_bfloat162*>(dst)[t * 2]     = p0;
    reinterpret_cast<__nv_bfloat162*>(dst)[t * 2 + 1] = p1;

    #pragma unroll
    for (int o = 16; o > 0; o >>= 1) s += __shfl_xor_sync(0xffffffffu, s, o);
    __shared__ float red[4];
    if ((t & 31) == 0) red[t >> 5] = s;
    __syncthreads();
    if (t == 0) {
        float n = sqrtf(red[0] + red[1] + red[2] + red[3]);
        if (isnew) { g_nnew[r] = n; g_rnew[r] = 1.0f / n; }
        else       { g_nex[r]  = n; g_rex[r]  = 1.0f / n; }
    }
}

// ---------------- K1b: fuse layers:  g_W = om @ fc  (512x512x512 fp32) -------
// Y[i,n] = sum_j om[i,j] * fc[j,n]; same tiling as k_gemm, B indexed K-major.
__global__ void __launch_bounds__(256) k_fuse(const float* __restrict__ om,
                                              const float* __restrict__ fc) {
    __shared__ float Xs[32 * 68];
    __shared__ float Fs[32 * 68];
    const int bm = blockIdx.x * 64, bn = blockIdx.y * 64;
    const int t = threadIdx.x, tx = t & 15, ty = t >> 4;
    float acc[4][4];
    #pragma unroll
    for (int i = 0; i < 4; i++)
        #pragma unroll
        for (int j = 0; j < 4; j++) acc[i][j] = 0.f;

    for (int j0 = 0; j0 < DIM; j0 += 32) {
        #pragma unroll
        for (int q = 0; q < 8; q++) {
            int i = t + q * 256;
            int rr = i >> 5, cc = i & 31;          // om tile: 64 rows x 32 j
            Xs[cc * 68 + rr] = om[(size_t)(bm + rr) * DIM + j0 + cc];
        }
        #pragma unroll
        for (int q = 0; q < 8; q++) {
            int i = t + q * 256;
            int rr = i >> 6, cc = i & 63;          // fc tile: 32 j x 64 cols
            Fs[rr * 68 + cc] = fc[(size_t)(j0 + rr) * DIM + bn + cc];
        }
        __syncthreads();
        #pragma unroll
        for (int k = 0; k < 32; k++) {
            float4 a  = *(const float4*)&Xs[k * 68 + ty * 4];
            float4 bb = *(const float4*)&Fs[k * 68 + tx * 4];
            float av[4] = {a.x, a.y, a.z, a.w};
            float bv[4] = {bb.x, bb.y, bb.z, bb.w};
            #pragma unroll
            for (int i = 0; i < 4; i++)
                #pragma unroll
                for (int j = 0; j < 4; j++) acc[i][j] += av[i] * bv[j];
        }
        __syncthreads();
    }
    #pragma unroll
    for (int i = 0; i < 4; i++) {
        float4 o;
        o.x = acc[i][0]; o.y = acc[i][1]; o.z = acc[i][2]; o.w = acc[i][3];
        *(float4*)&g_W[(size_t)(bm + ty * 4 + i) * DIM + bn + tx * 4] = o;
    }
}

// ---------------- K1c: fused bias  g_c = om @ fb + ob -------------------------
__global__ void k_cbias(const float* __restrict__ om, const float* __restrict__ fb,
                        const float* __restrict__ ob) {
    int wp = threadIdx.x >> 5, ln = threadIdx.x & 31;
    int row = blockIdx.x * 8 + wp;                 // grid 64 x 8 warps = 512 rows
    const float* orow = om + (size_t)row * DIM;
    float s = 0.f;
    for (int j = ln; j < DIM; j += 32) s += orow[j] * fb[j];
    #pragma unroll
    for (int o = 16; o > 0; o >>= 1) s += __shfl_xor_sync(0xffffffffu, s, o);
    if (ln == 0) g_c[row] = s + ob[row];
}

// ---------------- K2: mma.sync sim GEMM + in-register per-stream top-3 -------
#define MT 128
#define NT 128
#define NSPLIT 8
#define NITER (N_EXIST / (NSPLIT * NT))       // 32
#define NCHUNK (NITER * 4)                    // 128 k-chunks (k=128 each)

#define SM_A     0                            // 128 x 512 bf16 swizzled: 131072 B
#define SM_B     131072                       // 3 x (128 x 128 bf16) = 3 x 32768
#define SM_REX   229376                       // 128 floats
#define SMEM_K2  229888

__device__ __forceinline__ int swA(int r, int c16) {
    return r * 1024 + ((c16 ^ (r & 7)) << 4);
}
__device__ __forceinline__ int swB(int r, int c16) {
    return r * 256 + ((c16 ^ (r & 7)) << 4);
}

#define TOP3_UPD(s, vv, cc)                                          \
    do {                                                             \
        float _v = (vv);                                             \
        if (_v > tv3[s][2]) {                                        \
            if (_v > tv3[s][0]) {                                    \
                tv3[s][2] = tv3[s][1]; ti3[s][2] = ti3[s][1];        \
                tv3[s][1] = tv3[s][0]; ti3[s][1] = ti3[s][0];        \
                tv3[s][0] = _v;        ti3[s][0] = (cc);             \
            } else if (_v > tv3[s][1]) {                             \
                tv3[s][2] = tv3[s][1]; ti3[s][2] = ti3[s][1];        \
                tv3[s][1] = _v;        ti3[s][1] = (cc);             \
            } else {                                                 \
                tv3[s][2] = _v;        ti3[s][2] = (cc);             \
            }                                                        \
        }                                                            \
    } while (0)

__global__ void __launch_bounds__(256, 1) k_sim_topk() {
    extern __shared__ unsigned char sraw[];
    const uint32_t sb = (uint32_t)__cvta_generic_to_shared(sraw);
    float* rex_s = (float*)(sraw + SM_REX);

    const int tid  = threadIdx.x;
    const int warp = tid >> 5, lane = tid & 31;
    const int wm = warp & 1, wn = warp >> 1;
    const int g  = lane >> 2, tg = lane & 3;
    const int t4 = lane >> 3, l7 = lane & 7;
    const int m0    = blockIdx.x * MT;
    const int split = blockIdx.y;

    uint32_t aBase[4];
    #pragma unroll
    for (int mi = 0; mi < 4; mi++) {
        int rowA = wm * 64 + mi * 16 + (t4 & 1) * 8 + l7;
        aBase[mi] = sb + SM_A + rowA * 1024;
    }
    uint32_t bRow[2];
    #pragma unroll
    for (int nia = 0; nia < 2; nia++) {
        int rowB = wn * 32 + nia * 16 + (t4 >> 1) * 8 + l7;
        bRow[nia] = rowB * 256;
    }
    const int aC16base = (t4 >> 1);
    const int bC16base = (t4 & 1);

    float rn[8];
    #pragma unroll
    for (int s = 0; s < 8; s++)
        rn[s] = g_rnew[m0 + wm * 64 + (s >> 1) * 16 + (s & 1) * 8 + g];

    #pragma unroll 8
    for (int q = 0; q < 32; q++) {
        int u = tid + q * 256;
        int r = u >> 6, c16 = u & 63;
        cp16(sraw + SM_A + swA(r, c16), g_newb + (size_t)(m0 + r) * DIM + c16 * 8);
    }
    asm volatile("cp.async.commit_group;\n");

    #pragma unroll
    for (int pc = 0; pc < 2; pc++) {
        const int n0 = split * (NT * NITER);
        #pragma unroll
        for (int q = 0; q < 8; q++) {
            int u = tid + q * 256;
            int r = u >> 4, c16 = u & 15;
            cp16(sraw + SM_B + pc * 32768 + swB(r, c16),
                 g_exb + (size_t)(n0 + r) * DIM + pc * 128 + c16 * 8);
        }
        asm volatile("cp.async.commit_group;\n");
    }

    float tv3[8][3]; int ti3[8][3];
    #pragma unroll
    for (int s = 0; s < 8; s++)
        #pragma unroll
        for (int q = 0; q < 3; q++) { tv3[s][q] = -1e30f; ti3[s][q] = 0; }

    int gc = 0;
    #pragma unroll 1
    for (int it = 0; it < NITER; ++it) {
        const int n0 = split * (NT * NITER) + it * NT;

        float acc[4][4][4];
        #pragma unroll
        for (int a = 0; a < 4; a++)
            #pragma unroll
            for (int b = 0; b < 4; b++)
                #pragma unroll
                for (int c = 0; c < 4; c++) acc[a][b][c] = 0.f;

        #pragma unroll 1
        for (int kc = 0; kc < 4; kc++, gc++) {
            if (gc < NCHUNK - 1) asm volatile("cp.async.wait_group 1;\n");
            else                 asm volatile("cp.async.wait_group 0;\n");
            __syncthreads();

            if (kc == 0 && tid < NT) rex_s[tid] = g_rex[n0 + tid];

            if (gc + 2 < NCHUNK) {
                const int ng  = gc + 2;
                const int nit = ng >> 2, nkc = ng & 3;
                const int nn0 = split * (NT * NITER) + nit * NT;
                #pragma unroll
                for (int q = 0; q < 8; q++) {
                    int u = tid + q * 256;
                    int r = u >> 4, c16 = u & 15;
                    cp16(sraw + SM_B + (ng % 3) * 32768 + swB(r, c16),
                         g_exb + (size_t)(nn0 + r) * DIM + nkc * 128 + c16 * 8);
                }
                asm volatile("cp.async.commit_group;\n");
            }

            const uint32_t bBuf = sb + SM_B + (gc % 3) * 32768;
            #pragma unroll
            for (int ks = 0; ks < 8; ks++) {
                uint32_t afr[4][4], bfr[2][4];
                const int ac16 = kc * 16 + ks * 2 + aC16base;
                #pragma unroll
                for (int mi = 0; mi < 4; mi++)
                    ldsm4(afr[mi], aBase[mi] + (((uint32_t)(ac16 ^ l7)) << 4));
                const int bc16 = ks * 2 + bC16base;
                #pragma unroll
                for (int nia = 0; nia < 2; nia++)
                    ldsm4(bfr[nia], bBuf + bRow[nia] + (((uint32_t)(bc16 ^ l7)) << 4));
                #pragma unroll
                for (int mi = 0; mi < 4; mi++) {
                    mma16816(acc[mi][0], afr[mi], bfr[0]);
                    mma16816(acc[mi][1], afr[mi], bfr[0] + 2);
                    mma16816(acc[mi][2], afr[mi], bfr[1]);
                    mma16816(acc[mi][3], afr[mi], bfr[1] + 2);
                }
            }
        }

        #pragma unroll
        for (int ni = 0; ni < 4; ni++) {
            const int ct = wn * 32 + ni * 8 + tg * 2;
            const float e0 = rex_s[ct], e1 = rex_s[ct + 1];
            const int c0 = n0 + ct, c1 = c0 + 1;
            #pragma unroll
            for (int mi = 0; mi < 4; mi++) {
                TOP3_UPD(2 * mi,     acc[mi][ni][0] * rn[2 * mi] * e0,     c0);
                TOP3_UPD(2 * mi,     acc[mi][ni][1] * rn[2 * mi] * e1,     c1);
                TOP3_UPD(2 * mi + 1, acc[mi][ni][2] * rn[2 * mi + 1] * e0, c0);
                TOP3_UPD(2 * mi + 1, acc[mi][ni][3] * rn[2 * mi + 1] * e1, c1);
            }
        }
    }

    const int cth = wn * 4 + tg;
    #pragma unroll
    for (int s = 0; s < 8; s++) {
        int row = m0 + wm * 64 + (s >> 1) * 16 + (s & 1) * 8 + g;
        size_t base = ((size_t)row * NSPLIT + split) * 48 + cth * 3;
        #pragma unroll
        for (int q = 0; q < 3; q++) {
            g_pval[base + q] = tv3[s][q];
            g_pidx[base + q] = ti3[s][q];
        }
    }
}

// ---------------- K3: merge 384 candidates, exact rescore, top-3, aggregate --
__global__ void k_select(const float* __restrict__ xn, const float* __restrict__ xe) {
    const int row = blockIdx.x;
    const int t = threadIdx.x;   // 128 threads
    __shared__ float sv[128]; __shared__ int si[128];
    __shared__ float xrow[DIM];
    __shared__ int   cidx[8];
    __shared__ float csim[8];
    __shared__ float bsel[4]; __shared__ int bidx[3];

    float cv[3]; int ci[3]; bool tk[3] = {false, false, false};
    {
        size_t base = (size_t)row * 384 + t * 3;
        #pragma unroll
        for (int q = 0; q < 3; q++) { cv[q] = g_pval[base + q]; ci[q] = g_pidx[base + q]; }
    }

    for (int sel = 0; sel < 8; ++sel) {
        float lv = -1e30f; int lq = 0;
        #pragma unroll
        for (int q = 0; q < 3; q++)
            if (!tk[q] && cv[q] > lv) { lv = cv[q]; lq = q; }
        sv[t] = lv; si[t] = t * 4 + lq;
        __syncthreads();
        for (int s = 64; s > 0; s >>= 1) {
            if (t < s) { if (sv[t + s] > sv[t]) { sv[t] = sv[t + s]; si[t] = si[t + s]; } }
            __syncthreads();
        }
        int w = si[0];
        if (t == (w >> 2)) { tk[w & 3] = true; cidx[sel] = ci[w & 3]; }
        __syncthreads();
    }

    #pragma unroll
    for (int q = 0; q < 4; q++)
        xrow[t + q * 128] = xn[(size_t)row * DIM + t + q * 128];
    __syncthreads();

    int wp = t >> 5, ln = t & 31;
    for (int c = wp; c < 8; c += 4) {
        const float* er = xe + (size_t)cidx[c] * DIM;
        float s = 0.f;
        for (int j = ln; j < DIM; j += 32) s += xrow[j] * er[j];
        #pragma unroll
        for (int o = 16; o > 0; o >>= 1) s += __shfl_xor_sync(0xffffffffu, s, o);
        if (ln == 0) csim[c] = s / (g_nnew[row] * g_nex[cidx[c]] + EPSV);
    }
    __syncthreads();

    if (t == 0) {
        float bv[3] = {-1e30f, -1e30f, -1e30f}; int bi[3] = {0, 0, 0};
        for (int c = 0; c < 8; c++) {
            float vv = csim[c]; int ii = cidx[c];
            if (vv > bv[2]) {
                bv[2] = vv; bi[2] = ii;
                if (bv[2] > bv[1]) { float a = bv[1]; bv[1] = bv[2]; bv[2] = a; int b = bi[1]; bi[1] = bi[2]; bi[2] = b; }
                if (bv[1] > bv[0]) { float a = bv[0]; bv[0] = bv[1]; bv[1] = a; int b = bi[0]; bi[0] = bi[1]; bi[1] = b; }
            }
        }
        bsel[0] = bv[0]; bsel[1] = bv[1]; bsel[2] = bv[2];
        bsel[3] = bv[0] + bv[1] + bv[2];
        bidx[0] = bi[0]; bidx[1] = bi[1]; bidx[2] = bi[2];
    }
    __syncthreads();

    float w0 = bsel[0], w1 = bsel[1], w2 = bsel[2], ws = bsel[3];
    const float* e0 = xe + (size_t)bidx[0] * DIM;
    const float* e1 = xe + (size_t)bidx[1] * DIM;
    const float* e2 = xe + (size_t)bidx[2] * DIM;
    #pragma unroll
    for (int q = 0; q < 4; q++) {
        int e = t + q * 128;
        g_agg[(size_t)row * DIM + e] = (w0 * e0[e] + w1 * e1[e] + w2 * e2[e]) / ws;
    }
}

// ---------------- K4: single fused fp32 GEMM  out = agg @ g_W^T + g_c --------
__global__ void __launch_bounds__(256) k_gemm(float* __restrict__ outp) {
    const float* X = g_agg;
    const float* W = g_W;

    __shared__ float Xs[32 * 68];
    __shared__ float Ws[32 * 68];
    const int bm = blockIdx.x * 64, bn = blockIdx.y * 64;
    const int t = threadIdx.x, tx = t & 15, ty = t >> 4;
    float acc[4][4];
    #pragma unroll
    for (int i = 0; i < 4; i++)
        #pragma unroll
        for (int j = 0; j < 4; j++) acc[i][j] = 0.f;

    for (int k0 = 0; k0 < DIM; k0 += 32) {
        #pragma unroll
        for (int q = 0; q < 8; q++) {
            int i = t + q * 256;
            int rr = i >> 5, cc = i & 31;
            Xs[cc * 68 + rr] = X[(size_t)(bm + rr) * DIM + k0 + cc];
            Ws[cc * 68 + rr] = W[(size_t)(bn + rr) * DIM + k0 + cc];
        }
        __syncthreads();
        #pragma unroll
        for (int k = 0; k < 32; k++) {
            float4 a  = *(const float4*)&Xs[k * 68 + ty * 4];
            float4 bb = *(const float4*)&Ws[k * 68 + tx * 4];
            float av[4] = {a.x, a.y, a.z, a.w};
            float bv[4] = {bb.x, bb.y, bb.z, bb.w};
            #pragma unroll
            for (int i = 0; i < 4; i++)
                #pragma unroll
                for (int j = 0; j < 4; j++) acc[i][j] += av[i] * bv[j];
        }
        __syncthreads();
    }
    float4 bb = *(const float4*)&g_c[bn + tx * 4];
    float bvec[4] = {bb.x, bb.y, bb.z, bb.w};
    #pragma unroll
    for (int i = 0; i < 4; i++) {
        int m = bm + ty * 4 + i;
        float4 o;
        o.x = acc[i][0] + bvec[0]; o.y = acc[i][1] + bvec[1];
        o.z = acc[i][2] + bvec[2]; o.w = acc[i][3] + bvec[3];
        *(float4*)&outp[(size_t)m * DIM + bn + tx * 4] = o;
    }
}

// ---------------- launch ------------------------------------------------------
extern "C" void kernel_launch(void* const* d_in, const int* in_sizes, int n_in,
                              void* d_out, int out_size) {
    (void)in_sizes; (void)n_in; (void)out_size;
    const float* xn = (const float*)d_in[0];
    const float* xe = (const float*)d_in[1];
    const float* fw = (const float*)d_in[2];
    const float* fb = (const float*)d_in[3];
    const float* ow = (const float*)d_in[4];
    const float* ob = (const float*)d_in[5];
    float* out = (float*)d_out;

    k_norm_convert<<<N_NEW + N_EXIST, 128>>>(xn, xe);
    k_fuse<<<dim3(DIM / 64, DIM / 64), 256>>>(ow, fw);
    k_cbias<<<DIM / 8, 256>>>(ow, fb, ob);

    cudaFuncSetAttribute(k_sim_topk, cudaFuncAttributeMaxDynamicSharedMemorySize, SMEM_K2);
    k_sim_topk<<<dim3(N_NEW / MT, NSPLIT), 256, SMEM_K2>>>();

    k_select<<<N_NEW, 128>>>(xn, xe);

    k_gemm<<<dim3(N_NEW / 64, DIM / 64), 256>>>(out);
}